// round 15
// baseline (speedup 1.0000x reference)
#include <cuda_runtime.h>
#include <math.h>

#define DD 6
#define SEQ 128
typedef unsigned long long u64;

// per-batch K/V region: 64 key-pairs * 24 floats = 1536, +4 pad so the 4
// batch bases land in distinct 16B bank-quads
#define KV_STRIDE 1540

__device__ __forceinline__ u64 pack2(float lo, float hi) {
    u64 r; asm("mov.b64 %0, {%1, %2};" : "=l"(r) : "f"(lo), "f"(hi)); return r;
}
__device__ __forceinline__ void unpack2(u64 v, float& lo, float& hi) {
    asm("mov.b64 {%0, %1}, %2;" : "=f"(lo), "=f"(hi) : "l"(v));
}
__device__ __forceinline__ u64 ffma2(u64 a, u64 b, u64 c) {
    u64 d; asm("fma.rn.f32x2 %0, %1, %2, %3;" : "=l"(d) : "l"(a), "l"(b), "l"(c)); return d;
}
__device__ __forceinline__ u64 fmul2(u64 a, u64 b) {
    u64 d; asm("mul.rn.f32x2 %0, %1, %2;" : "=l"(d) : "l"(a), "l"(b)); return d;
}
__device__ __forceinline__ u64 fadd2(u64 a, u64 b) {
    u64 d; asm("add.rn.f32x2 %0, %1, %2;" : "=l"(d) : "l"(a), "l"(b)); return d;
}
__device__ __forceinline__ float ex2f(float x) {
    float y; asm("ex2.approx.f32 %0, %1;" : "=f"(y) : "f"(x)); return y;
}
__device__ __forceinline__ float rcpf(float x) {
    float y; asm("rcp.approx.f32 %0, %1;" : "=f"(y) : "f"(x)); return y;
}

// duplicated-lane weight offsets in u64 units: each entry = (w,w)
#define WQ   0      // 108
#define BQ   108    // 18
#define WO   126    // 36
#define BO   162    // 6
#define W1   168    // 36
#define B1   204    // 6
#define W2   210    // 36
#define B2   246    // 6
#define L1WO 252    // 6
#define L1BO 258    // 6
#define L2WO 264    // 6
#define L2BO 270    // 6

__device__ __forceinline__ u64 dot6(const u64* q, ulonglong2 K0, ulonglong2 K1, ulonglong2 K2) {
    return ffma2(q[0], K0.x,
           ffma2(q[1], K0.y,
           ffma2(q[2], K1.x,
           ffma2(q[3], K1.y,
           ffma2(q[4], K2.x,
           fmul2(q[5], K2.y))))));
}

// load token-pair x (24B stride tokens: A at xt[0..5], B at xt[6..11]) packed (A,B)
__device__ __forceinline__ void load_x_packed(const float* __restrict__ xt, u64* xp) {
    const float4* p = (const float4*)xt;
    float4 X0 = p[0], X1 = p[1], X2 = p[2];
    xp[0] = pack2(X0.x, X1.z); xp[1] = pack2(X0.y, X1.w);
    xp[2] = pack2(X0.z, X2.x); xp[3] = pack2(X0.w, X2.y);
    xp[4] = pack2(X1.x, X2.z); xp[5] = pack2(X1.y, X2.w);
}

// LN1 + K/V projection for tokens (2uu, 2uu+1), all packed over (A,B).
// Returns h (packed LN1 output) for later q construction.
__device__ __forceinline__ void prologue_pair(
    const float* __restrict__ xt, float* __restrict__ kv_row,
    const u64* __restrict__ W, u64* __restrict__ h)
{
    u64 xp[DD];
    load_x_packed(xt, xp);
    const u64 sixth2 = pack2(1.f / DD, 1.f / DD);
    u64 s = xp[0];
#pragma unroll
    for (int d = 1; d < DD; ++d) s = fadd2(s, xp[d]);
    u64 nm = fmul2(s, pack2(-1.f / DD, -1.f / DD));
    u64 var = 0ull, dm[DD];
#pragma unroll
    for (int d = 0; d < DD; ++d) { dm[d] = fadd2(xp[d], nm); var = ffma2(dm[d], dm[d], var); }
    float vA, vB;
    unpack2(fmul2(var, sixth2), vA, vB);
    u64 rstd = pack2(rsqrtf(vA + 1e-5f), rsqrtf(vB + 1e-5f));
#pragma unroll
    for (int d = 0; d < DD; ++d)
        h[d] = ffma2(fmul2(dm[d], rstd), W[L1WO + d], W[L1BO + d]);
    // K,V projection (wqkv columns 6..17), packed (A,B) == pair-interleaved layout
    u64 kv[12];
#pragma unroll
    for (int j = 0; j < 12; ++j) {
        u64 a = W[BQ + 6 + j];
#pragma unroll
        for (int i = 0; i < DD; ++i) a = ffma2(h[i], W[WQ + i * 18 + 6 + j], a);
        kv[j] = a;
    }
    ulonglong2* pp = (ulonglong2*)kv_row;
#pragma unroll
    for (int i = 0; i < 6; ++i) pp[i] = make_ulonglong2(kv[2 * i], kv[2 * i + 1]);
}

// q for both tokens from packed h; outputs duplicated-lane (a,a)/(b,b)
__device__ __forceinline__ void make_q(
    const u64* __restrict__ h, const u64* __restrict__ W,
    u64* __restrict__ qa2, u64* __restrict__ qb2)
{
    const float SCL = 0.58897937652f;   // (1/sqrt6)*log2(e)
    const u64 scl2 = pack2(SCL, SCL);
#pragma unroll
    for (int j = 0; j < DD; ++j) {
        u64 a = W[BQ + j];
#pragma unroll
        for (int i = 0; i < DD; ++i) a = ffma2(h[i], W[WQ + i * 18 + j], a);
        a = fmul2(a, scl2);
        float qA, qB;
        unpack2(a, qA, qB);
        qa2[j] = pack2(qA, qA);
        qb2[j] = pack2(qB, qB);
    }
}

// causal attention for query-pair uu; keys-in-lanes. UNCHANGED from R14.
__device__ __forceinline__ void attend(
    int uu, const u64* __restrict__ qa2, const u64* __restrict__ qb2,
    const float* __restrict__ kv_base, u64* __restrict__ o2)
{
    const ulonglong2* kvb = (const ulonglong2*)kv_base;
    u64 acca[DD], accb[DD];
#pragma unroll
    for (int d = 0; d < DD; ++d) { acca[d] = 0ull; accb[d] = 0ull; }
    u64 la2 = 0ull, lb2 = 0ull;

#pragma unroll 2
    for (int j = 0; j < uu; ++j) {
        const ulonglong2* p = kvb + j * 6;
        ulonglong2 K0 = p[0], K1 = p[1], K2 = p[2];
        ulonglong2 V0 = p[3], V1 = p[4], V2 = p[5];
        u64 sa = dot6(qa2, K0, K1, K2);
        u64 sb = dot6(qb2, K0, K1, K2);
        float saA, saB, sbA, sbB;
        unpack2(sa, saA, saB); unpack2(sb, sbA, sbB);
        u64 pa = pack2(ex2f(saA), ex2f(saB));
        u64 pb = pack2(ex2f(sbA), ex2f(sbB));
        la2 = fadd2(la2, pa); lb2 = fadd2(lb2, pb);
        acca[0] = ffma2(pa, V0.x, acca[0]); accb[0] = ffma2(pb, V0.x, accb[0]);
        acca[1] = ffma2(pa, V0.y, acca[1]); accb[1] = ffma2(pb, V0.y, accb[1]);
        acca[2] = ffma2(pa, V1.x, acca[2]); accb[2] = ffma2(pb, V1.x, accb[2]);
        acca[3] = ffma2(pa, V1.y, acca[3]); accb[3] = ffma2(pb, V1.y, accb[3]);
        acca[4] = ffma2(pa, V2.x, acca[4]); accb[4] = ffma2(pb, V2.x, accb[4]);
        acca[5] = ffma2(pa, V2.y, acca[5]); accb[5] = ffma2(pb, V2.y, accb[5]);
    }
    // diagonal key-pair: query 2uu masks key 2uu+1
    {
        const ulonglong2* p = kvb + uu * 6;
        ulonglong2 K0 = p[0], K1 = p[1], K2 = p[2];
        ulonglong2 V0 = p[3], V1 = p[4], V2 = p[5];
        u64 sa = dot6(qa2, K0, K1, K2);
        u64 sb = dot6(qb2, K0, K1, K2);
        float saA, saB, sbA, sbB;
        unpack2(sa, saA, saB); unpack2(sb, sbA, sbB);
        (void)saB;
        u64 pa = pack2(ex2f(saA), 0.0f);
        u64 pb = pack2(ex2f(sbA), ex2f(sbB));
        la2 = fadd2(la2, pa); lb2 = fadd2(lb2, pb);
        acca[0] = ffma2(pa, V0.x, acca[0]); accb[0] = ffma2(pb, V0.x, accb[0]);
        acca[1] = ffma2(pa, V0.y, acca[1]); accb[1] = ffma2(pb, V0.y, accb[1]);
        acca[2] = ffma2(pa, V1.x, acca[2]); accb[2] = ffma2(pb, V1.x, accb[2]);
        acca[3] = ffma2(pa, V1.y, acca[3]); accb[3] = ffma2(pb, V1.y, accb[3]);
        acca[4] = ffma2(pa, V2.x, acca[4]); accb[4] = ffma2(pb, V2.x, accb[4]);
        acca[5] = ffma2(pa, V2.y, acca[5]); accb[5] = ffma2(pb, V2.y, accb[5]);
    }

    float lo, hi;
    unpack2(la2, lo, hi); float la = lo + hi;
    unpack2(lb2, lo, hi); float lb = lo + hi;
    float inva = rcpf(la), invb = rcpf(lb);
    // o2[d] = packed (oA_d, oB_d)
#pragma unroll
    for (int d = 0; d < DD; ++d) {
        unpack2(acca[d], lo, hi); float oA = (lo + hi) * inva;
        unpack2(accb[d], lo, hi); float oB = (lo + hi) * invb;
        o2[d] = pack2(oA, oB);
    }
}

// out-proj + residual + LN2 + FFN + residual for the token PAIR, packed (A,B).
// Reloads x from global (L2 hit). __noinline__ confines register appetite.
__device__ __noinline__ void epilogue_pair(
    const u64* __restrict__ o2,
    const float* __restrict__ xt, float* __restrict__ ot,
    const u64* __restrict__ W)
{
    u64 xp[DD];
    load_x_packed(xt, xp);
    u64 y[DD];
#pragma unroll
    for (int d = 0; d < DD; ++d) {
        u64 a = W[BO + d];
#pragma unroll
        for (int i = 0; i < DD; ++i) a = ffma2(o2[i], W[WO + i * 6 + d], a);
        y[d] = fadd2(xp[d], a);
    }
    const u64 sixth2 = pack2(1.f / DD, 1.f / DD);
    u64 s = y[0];
#pragma unroll
    for (int d = 1; d < DD; ++d) s = fadd2(s, y[d]);
    u64 nm = fmul2(s, pack2(-1.f / DD, -1.f / DD));
    u64 var = 0ull, dm[DD];
#pragma unroll
    for (int d = 0; d < DD; ++d) { dm[d] = fadd2(y[d], nm); var = ffma2(dm[d], dm[d], var); }
    float vA, vB;
    unpack2(fmul2(var, sixth2), vA, vB);
    u64 rstd = pack2(rsqrtf(vA + 1e-5f), rsqrtf(vB + 1e-5f));
    u64 h[DD];
#pragma unroll
    for (int d = 0; d < DD; ++d)
        h[d] = ffma2(fmul2(dm[d], rstd), W[L2WO + d], W[L2BO + d]);
    u64 g[DD];
#pragma unroll
    for (int d = 0; d < DD; ++d) {
        u64 a = W[B1 + d];
#pragma unroll
        for (int i = 0; i < DD; ++i) a = ffma2(h[i], W[W1 + i * 6 + d], a);
        float aA, aB;
        unpack2(a, aA, aB);
        g[d] = pack2(aA * normcdff(aA), aB * normcdff(aB));   // exact gelu
    }
    float yA[DD], yB[DD];
#pragma unroll
    for (int d = 0; d < DD; ++d) {
        u64 a = W[B2 + d];
#pragma unroll
        for (int i = 0; i < DD; ++i) a = ffma2(g[i], W[W2 + i * 6 + d], a);
        u64 f = fadd2(y[d], a);
        unpack2(f, yA[d], yB[d]);
    }
    float4* op = (float4*)ot;
    op[0] = make_float4(yA[0], yA[1], yA[2], yA[3]);
    op[1] = make_float4(yA[4], yA[5], yB[0], yB[1]);
    op[2] = make_float4(yB[2], yB[3], yB[4], yB[5]);
}

__global__ __launch_bounds__(128, 4) void block_ffn_kernel(
    const float* __restrict__ x,
    const float* __restrict__ ln1_w, const float* __restrict__ ln1_b,
    const float* __restrict__ wqkv,  const float* __restrict__ bqkv,
    const float* __restrict__ wo,    const float* __restrict__ bo,
    const float* __restrict__ ln2_w, const float* __restrict__ ln2_b,
    const float* __restrict__ w1,    const float* __restrict__ b1,
    const float* __restrict__ w2,    const float* __restrict__ b2,
    float* __restrict__ out)
{
    __shared__ __align__(16) float s_kv[4 * KV_STRIDE];   // 4 batches, pair-interleaved
    __shared__ u64 s_wd[276];                              // duplicated-lane weights

    const int t = threadIdx.x;
    const int b = t & 3;              // batch slot (interleaved in warp)
    const int u = t >> 2;             // first query-pair index, 0..31
    const int v = 63 - u;             // second query-pair (triangle fold)
    const int batch = blockIdx.x * 4 + b;

    // ---- stage duplicated-lane weights ----
    for (int idx = t; idx < 276; idx += 128) {
        float w;
        if      (idx < 108) w = wqkv[idx];
        else if (idx < 126) w = bqkv[idx - 108];
        else if (idx < 162) w = wo[idx - 126];
        else if (idx < 168) w = bo[idx - 162];
        else if (idx < 204) w = w1[idx - 168];
        else if (idx < 210) w = b1[idx - 204];
        else if (idx < 246) w = w2[idx - 210];
        else if (idx < 252) w = b2[idx - 246];
        else if (idx < 258) w = ln1_w[idx - 252];
        else if (idx < 264) w = ln1_b[idx - 258];
        else if (idx < 270) w = ln2_w[idx - 264];
        else                w = ln2_b[idx - 270];
        s_wd[idx] = pack2(w, w);
    }
    __syncthreads();   // weights visible

    const float* xb = x   + (long)batch * SEQ * DD;
    float*       ob = out + (long)batch * SEQ * DD;
    float* kvbase = s_kv + b * KV_STRIDE;

    // ---- packed prologues for both query-pairs; K/V rows u and v ----
    u64 h1[DD], h2[DD];
    prologue_pair(xb + 2 * u * DD, kvbase + u * 24, s_wd, h1);
    prologue_pair(xb + 2 * v * DD, kvbase + v * 24, s_wd, h2);

    u64 qa2[DD], qb2[DD];
    make_q(h1, s_wd, qa2, qb2);

    __syncthreads();   // all K/V visible

    // ---- pair u ----
    {
        u64 o2[DD];
        attend(u, qa2, qb2, kvbase, o2);
        epilogue_pair(o2, xb + 2 * u * DD, ob + 2 * u * DD, s_wd);
    }

    // ---- pair v = 63-u ----
    make_q(h2, s_wd, qa2, qb2);
    {
        u64 o2[DD];
        attend(v, qa2, qb2, kvbase, o2);
        epilogue_pair(o2, xb + 2 * v * DD, ob + 2 * v * DD, s_wd);
    }
}

extern "C" void kernel_launch(void* const* d_in, const int* in_sizes, int n_in,
                              void* d_out, int out_size) {
    const float* x     = (const float*)d_in[0];
    const float* ln1_w = (const float*)d_in[1];
    const float* ln1_b = (const float*)d_in[2];
    const float* wqkv  = (const float*)d_in[3];
    const float* bqkv  = (const float*)d_in[4];
    const float* wo    = (const float*)d_in[5];
    const float* bo    = (const float*)d_in[6];
    const float* ln2_w = (const float*)d_in[7];
    const float* ln2_b = (const float*)d_in[8];
    const float* w1    = (const float*)d_in[9];
    const float* b1    = (const float*)d_in[10];
    const float* w2    = (const float*)d_in[11];
    const float* b2    = (const float*)d_in[12];
    float* out = (float*)d_out;

    const int B = in_sizes[0] / (SEQ * DD);   // 8192
    block_ffn_kernel<<<B / 4, 128>>>(x, ln1_w, ln1_b, wqkv, bqkv, wo, bo,
                                     ln2_w, ln2_b, w1, b1, w2, b2, out);
}

// round 17
// speedup vs baseline: 1.0061x; 1.0061x over previous
#include <cuda_runtime.h>
#include <math.h>

#define DD 6
#define SEQ 128
typedef unsigned long long u64;

// per-batch K/V region: 64 key-pairs * 24 floats = 1536, +4 pad so the 4
// batch bases land in distinct 16B bank-quads
#define KV_STRIDE 1540

__device__ __forceinline__ u64 pack2(float lo, float hi) {
    u64 r; asm("mov.b64 %0, {%1, %2};" : "=l"(r) : "f"(lo), "f"(hi)); return r;
}
__device__ __forceinline__ void unpack2(u64 v, float& lo, float& hi) {
    asm("mov.b64 {%0, %1}, %2;" : "=f"(lo), "=f"(hi) : "l"(v));
}
__device__ __forceinline__ u64 ffma2(u64 a, u64 b, u64 c) {
    u64 d; asm("fma.rn.f32x2 %0, %1, %2, %3;" : "=l"(d) : "l"(a), "l"(b), "l"(c)); return d;
}
__device__ __forceinline__ u64 fmul2(u64 a, u64 b) {
    u64 d; asm("mul.rn.f32x2 %0, %1, %2;" : "=l"(d) : "l"(a), "l"(b)); return d;
}
__device__ __forceinline__ u64 fadd2(u64 a, u64 b) {
    u64 d; asm("add.rn.f32x2 %0, %1, %2;" : "=l"(d) : "l"(a), "l"(b)); return d;
}
__device__ __forceinline__ float ex2f(float x) {
    float y; asm("ex2.approx.f32 %0, %1;" : "=f"(y) : "f"(x)); return y;
}
__device__ __forceinline__ float rcpf(float x) {
    float y; asm("rcp.approx.f32 %0, %1;" : "=f"(y) : "f"(x)); return y;
}

// duplicated-lane weight offsets in u64 units (ALL row bases even -> 16B aligned)
#define WQ   0      // 108  [6][18]
#define BQ   108    // 18
#define WO   126    // 36   [6][6]
#define BO   162    // 6
#define W1   168    // 36
#define B1   204    // 6
#define W2   210    // 36
#define B2   246    // 6
#define L1WO 252    // 6
#define L1BO 258    // 6
#define L2WO 264    // 6
#define L2BO 270    // 6

__device__ __forceinline__ u64 dot6(const u64* q, ulonglong2 K0, ulonglong2 K1, ulonglong2 K2) {
    return ffma2(q[0], K0.x,
           ffma2(q[1], K0.y,
           ffma2(q[2], K1.x,
           ffma2(q[3], K1.y,
           ffma2(q[4], K2.x,
           fmul2(q[5], K2.y))))));
}

// load token-pair x (A at xt[0..5], B at xt[6..11]) packed (A,B)
__device__ __forceinline__ void load_x_packed(const float* __restrict__ xt, u64* xp) {
    const float4* p = (const float4*)xt;
    float4 X0 = p[0], X1 = p[1], X2 = p[2];
    xp[0] = pack2(X0.x, X1.z); xp[1] = pack2(X0.y, X1.w);
    xp[2] = pack2(X0.z, X2.x); xp[3] = pack2(X0.w, X2.y);
    xp[4] = pack2(X1.x, X2.z); xp[5] = pack2(X1.y, X2.w);
}

// LN1 on packed x -> packed h
__device__ __forceinline__ void ln1(const u64* xp, const u64* __restrict__ W, u64* h) {
    const u64 sixth2 = pack2(1.f / DD, 1.f / DD);
    u64 s = xp[0];
#pragma unroll
    for (int d = 1; d < DD; ++d) s = fadd2(s, xp[d]);
    u64 nm = fmul2(s, pack2(-1.f / DD, -1.f / DD));
    u64 var = 0ull, dm[DD];
#pragma unroll
    for (int d = 0; d < DD; ++d) { dm[d] = fadd2(xp[d], nm); var = ffma2(dm[d], dm[d], var); }
    float vA, vB;
    unpack2(fmul2(var, sixth2), vA, vB);
    u64 rstd = pack2(rsqrtf(vA + 1e-5f), rsqrtf(vB + 1e-5f));
#pragma unroll
    for (int d = 0; d < DD; ++d)
        h[d] = ffma2(fmul2(dm[d], rstd), W[L1WO + d], W[L1BO + d]);
}

// Full prologue for pair u: LN1 + full 18-col QKV pass (row-walk LDS.128),
// emits duplicated-lane q and writes the K/V row.
__device__ __forceinline__ void prologue_full(
    const float* __restrict__ xt, float* __restrict__ kv_row,
    const u64* __restrict__ W, u64* __restrict__ qa2, u64* __restrict__ qb2)
{
    u64 xp[DD];
    load_x_packed(xt, xp);
    u64 h[DD];
    ln1(xp, W, h);

    u64 acc[18];
    const ulonglong2* Bp = (const ulonglong2*)(W + BQ);
#pragma unroll
    for (int k = 0; k < 9; ++k) { ulonglong2 bb = Bp[k]; acc[2 * k] = bb.x; acc[2 * k + 1] = bb.y; }
    const ulonglong2* Wp = (const ulonglong2*)(W + WQ);
#pragma unroll
    for (int i = 0; i < DD; ++i) {
#pragma unroll
        for (int k = 0; k < 9; ++k) {
            ulonglong2 w = Wp[i * 9 + k];
            acc[2 * k]     = ffma2(h[i], w.x, acc[2 * k]);
            acc[2 * k + 1] = ffma2(h[i], w.y, acc[2 * k + 1]);
        }
    }
    const float SCL = 0.58897937652f;   // (1/sqrt6)*log2(e)
    const u64 scl2 = pack2(SCL, SCL);
#pragma unroll
    for (int j = 0; j < DD; ++j) {
        float qA, qB;
        unpack2(fmul2(acc[j], scl2), qA, qB);
        qa2[j] = pack2(qA, qA);
        qb2[j] = pack2(qB, qB);
    }
    ulonglong2* pp = (ulonglong2*)kv_row;
#pragma unroll
    for (int i = 0; i < 6; ++i) pp[i] = make_ulonglong2(acc[6 + 2 * i], acc[7 + 2 * i]);
}

// K/V-only prologue for pair v (cols 6..17); returns h for deferred q.
__device__ __forceinline__ void prologue_kv(
    const float* __restrict__ xt, float* __restrict__ kv_row,
    const u64* __restrict__ W, u64* __restrict__ h)
{
    u64 xp[DD];
    load_x_packed(xt, xp);
    ln1(xp, W, h);

    u64 acc[12];
    const ulonglong2* Bp = (const ulonglong2*)(W + BQ + 6);
#pragma unroll
    for (int k = 0; k < 6; ++k) { ulonglong2 bb = Bp[k]; acc[2 * k] = bb.x; acc[2 * k + 1] = bb.y; }
#pragma unroll
    for (int i = 0; i < DD; ++i) {
        const ulonglong2* Wr = (const ulonglong2*)(W + WQ + i * 18 + 6);
#pragma unroll
        for (int k = 0; k < 6; ++k) {
            ulonglong2 w = Wr[k];
            acc[2 * k]     = ffma2(h[i], w.x, acc[2 * k]);
            acc[2 * k + 1] = ffma2(h[i], w.y, acc[2 * k + 1]);
        }
    }
    ulonglong2* pp = (ulonglong2*)kv_row;
#pragma unroll
    for (int i = 0; i < 6; ++i) pp[i] = make_ulonglong2(acc[2 * i], acc[2 * i + 1]);
}

// q from kept h (cols 0..5, row-walk)
__device__ __forceinline__ void make_q(
    const u64* __restrict__ h, const u64* __restrict__ W,
    u64* __restrict__ qa2, u64* __restrict__ qb2)
{
    u64 acc[6];
    const ulonglong2* Bp = (const ulonglong2*)(W + BQ);
#pragma unroll
    for (int k = 0; k < 3; ++k) { ulonglong2 bb = Bp[k]; acc[2 * k] = bb.x; acc[2 * k + 1] = bb.y; }
#pragma unroll
    for (int i = 0; i < DD; ++i) {
        const ulonglong2* Wr = (const ulonglong2*)(W + WQ + i * 18);
#pragma unroll
        for (int k = 0; k < 3; ++k) {
            ulonglong2 w = Wr[k];
            acc[2 * k]     = ffma2(h[i], w.x, acc[2 * k]);
            acc[2 * k + 1] = ffma2(h[i], w.y, acc[2 * k + 1]);
        }
    }
    const float SCL = 0.58897937652f;
    const u64 scl2 = pack2(SCL, SCL);
#pragma unroll
    for (int j = 0; j < DD; ++j) {
        float qA, qB;
        unpack2(fmul2(acc[j], scl2), qA, qB);
        qa2[j] = pack2(qA, qA);
        qb2[j] = pack2(qB, qB);
    }
}

// causal attention for query-pair uu; keys-in-lanes. UNCHANGED.
__device__ __forceinline__ void attend(
    int uu, const u64* __restrict__ qa2, const u64* __restrict__ qb2,
    const float* __restrict__ kv_base, u64* __restrict__ o2)
{
    const ulonglong2* kvb = (const ulonglong2*)kv_base;
    u64 acca[DD], accb[DD];
#pragma unroll
    for (int d = 0; d < DD; ++d) { acca[d] = 0ull; accb[d] = 0ull; }
    u64 la2 = 0ull, lb2 = 0ull;

#pragma unroll 2
    for (int j = 0; j < uu; ++j) {
        const ulonglong2* p = kvb + j * 6;
        ulonglong2 K0 = p[0], K1 = p[1], K2 = p[2];
        ulonglong2 V0 = p[3], V1 = p[4], V2 = p[5];
        u64 sa = dot6(qa2, K0, K1, K2);
        u64 sb = dot6(qb2, K0, K1, K2);
        float saA, saB, sbA, sbB;
        unpack2(sa, saA, saB); unpack2(sb, sbA, sbB);
        u64 pa = pack2(ex2f(saA), ex2f(saB));
        u64 pb = pack2(ex2f(sbA), ex2f(sbB));
        la2 = fadd2(la2, pa); lb2 = fadd2(lb2, pb);
        acca[0] = ffma2(pa, V0.x, acca[0]); accb[0] = ffma2(pb, V0.x, accb[0]);
        acca[1] = ffma2(pa, V0.y, acca[1]); accb[1] = ffma2(pb, V0.y, accb[1]);
        acca[2] = ffma2(pa, V1.x, acca[2]); accb[2] = ffma2(pb, V1.x, accb[2]);
        acca[3] = ffma2(pa, V1.y, acca[3]); accb[3] = ffma2(pb, V1.y, accb[3]);
        acca[4] = ffma2(pa, V2.x, acca[4]); accb[4] = ffma2(pb, V2.x, accb[4]);
        acca[5] = ffma2(pa, V2.y, acca[5]); accb[5] = ffma2(pb, V2.y, accb[5]);
    }
    // diagonal key-pair: query 2uu masks key 2uu+1
    {
        const ulonglong2* p = kvb + uu * 6;
        ulonglong2 K0 = p[0], K1 = p[1], K2 = p[2];
        ulonglong2 V0 = p[3], V1 = p[4], V2 = p[5];
        u64 sa = dot6(qa2, K0, K1, K2);
        u64 sb = dot6(qb2, K0, K1, K2);
        float saA, saB, sbA, sbB;
        unpack2(sa, saA, saB); unpack2(sb, sbA, sbB);
        (void)saB;
        u64 pa = pack2(ex2f(saA), 0.0f);
        u64 pb = pack2(ex2f(sbA), ex2f(sbB));
        la2 = fadd2(la2, pa); lb2 = fadd2(lb2, pb);
        acca[0] = ffma2(pa, V0.x, acca[0]); accb[0] = ffma2(pb, V0.x, accb[0]);
        acca[1] = ffma2(pa, V0.y, acca[1]); accb[1] = ffma2(pb, V0.y, accb[1]);
        acca[2] = ffma2(pa, V1.x, acca[2]); accb[2] = ffma2(pb, V1.x, accb[2]);
        acca[3] = ffma2(pa, V1.y, acca[3]); accb[3] = ffma2(pb, V1.y, accb[3]);
        acca[4] = ffma2(pa, V2.x, acca[4]); accb[4] = ffma2(pb, V2.x, accb[4]);
        acca[5] = ffma2(pa, V2.y, acca[5]); accb[5] = ffma2(pb, V2.y, accb[5]);
    }

    float lo, hi;
    unpack2(la2, lo, hi); float la = lo + hi;
    unpack2(lb2, lo, hi); float lb = lo + hi;
    float inva = rcpf(la), invb = rcpf(lb);
#pragma unroll
    for (int d = 0; d < DD; ++d) {
        unpack2(acca[d], lo, hi); float oA = (lo + hi) * inva;
        unpack2(accb[d], lo, hi); float oB = (lo + hi) * invb;
        o2[d] = pack2(oA, oB);
    }
}

// generic packed 6x6 GEMM: acc[d] = Brow[d] + sum_i in[i]*Wrow_i[d] (row-walk)
__device__ __forceinline__ void gemm6(
    const u64* __restrict__ in, const u64* __restrict__ W,
    int wofs, int bofs, u64* __restrict__ o)
{
    const ulonglong2* Bp = (const ulonglong2*)(W + bofs);
#pragma unroll
    for (int k = 0; k < 3; ++k) { ulonglong2 bb = Bp[k]; o[2 * k] = bb.x; o[2 * k + 1] = bb.y; }
#pragma unroll
    for (int i = 0; i < DD; ++i) {
        const ulonglong2* Wr = (const ulonglong2*)(W + wofs + i * 6);
#pragma unroll
        for (int k = 0; k < 3; ++k) {
            ulonglong2 w = Wr[k];
            o[2 * k]     = ffma2(in[i], w.x, o[2 * k]);
            o[2 * k + 1] = ffma2(in[i], w.y, o[2 * k + 1]);
        }
    }
}

// out-proj + residual + LN2 + FFN + residual for the token PAIR, packed (A,B).
__device__ __noinline__ void epilogue_pair(
    const u64* __restrict__ o2,
    const float* __restrict__ xt, float* __restrict__ ot,
    const u64* __restrict__ W)
{
    u64 xp[DD];
    load_x_packed(xt, xp);
    u64 y[DD];
    gemm6(o2, W, WO, BO, y);
#pragma unroll
    for (int d = 0; d < DD; ++d) y[d] = fadd2(xp[d], y[d]);

    const u64 sixth2 = pack2(1.f / DD, 1.f / DD);
    u64 s = y[0];
#pragma unroll
    for (int d = 1; d < DD; ++d) s = fadd2(s, y[d]);
    u64 nm = fmul2(s, pack2(-1.f / DD, -1.f / DD));
    u64 var = 0ull, dm[DD];
#pragma unroll
    for (int d = 0; d < DD; ++d) { dm[d] = fadd2(y[d], nm); var = ffma2(dm[d], dm[d], var); }
    float vA, vB;
    unpack2(fmul2(var, sixth2), vA, vB);
    u64 rstd = pack2(rsqrtf(vA + 1e-5f), rsqrtf(vB + 1e-5f));
    u64 h[DD];
#pragma unroll
    for (int d = 0; d < DD; ++d)
        h[d] = ffma2(fmul2(dm[d], rstd), W[L2WO + d], W[L2BO + d]);

    u64 g[DD];
    gemm6(h, W, W1, B1, g);
#pragma unroll
    for (int d = 0; d < DD; ++d) {
        float aA, aB;
        unpack2(g[d], aA, aB);
        g[d] = pack2(aA * normcdff(aA), aB * normcdff(aB));   // exact gelu
    }
    u64 f[DD];
    gemm6(g, W, W2, B2, f);
    float yA[DD], yB[DD];
#pragma unroll
    for (int d = 0; d < DD; ++d) {
        u64 r = fadd2(y[d], f[d]);
        unpack2(r, yA[d], yB[d]);
    }
    float4* op = (float4*)ot;
    op[0] = make_float4(yA[0], yA[1], yA[2], yA[3]);
    op[1] = make_float4(yA[4], yA[5], yB[0], yB[1]);
    op[2] = make_float4(yB[2], yB[3], yB[4], yB[5]);
}

__global__ __launch_bounds__(128, 4) void block_ffn_kernel(
    const float* __restrict__ x,
    const float* __restrict__ ln1_w, const float* __restrict__ ln1_b,
    const float* __restrict__ wqkv,  const float* __restrict__ bqkv,
    const float* __restrict__ wo,    const float* __restrict__ bo,
    const float* __restrict__ ln2_w, const float* __restrict__ ln2_b,
    const float* __restrict__ w1,    const float* __restrict__ b1,
    const float* __restrict__ w2,    const float* __restrict__ b2,
    float* __restrict__ out)
{
    __shared__ __align__(16) float s_kv[4 * KV_STRIDE];   // 4 batches, pair-interleaved
    __shared__ __align__(16) u64 s_wd[276];               // duplicated-lane weights

    const int t = threadIdx.x;
    const int b = t & 3;              // batch slot (interleaved in warp)
    const int u = t >> 2;             // first query-pair index, 0..31
    const int v = 63 - u;             // second query-pair (triangle fold)
    const int batch = blockIdx.x * 4 + b;

    // ---- stage duplicated-lane weights ----
    for (int idx = t; idx < 276; idx += 128) {
        float w;
        if      (idx < 108) w = wqkv[idx];
        else if (idx < 126) w = bqkv[idx - 108];
        else if (idx < 162) w = wo[idx - 126];
        else if (idx < 168) w = bo[idx - 162];
        else if (idx < 204) w = w1[idx - 168];
        else if (idx < 210) w = b1[idx - 204];
        else if (idx < 246) w = w2[idx - 210];
        else if (idx < 252) w = b2[idx - 246];
        else if (idx < 258) w = ln1_w[idx - 252];
        else if (idx < 264) w = ln1_b[idx - 258];
        else if (idx < 270) w = ln2_w[idx - 264];
        else                w = ln2_b[idx - 270];
        s_wd[idx] = pack2(w, w);
    }
    __syncthreads();   // weights visible

    const float* xb = x   + (long)batch * SEQ * DD;
    float*       ob = out + (long)batch * SEQ * DD;
    float* kvbase = s_kv + b * KV_STRIDE;

    // ---- prologues: pair u (full, q produced) and pair v (kv only, h kept) ----
    u64 qa2[DD], qb2[DD], h2[DD];
    prologue_full(xb + 2 * u * DD, kvbase + u * 24, s_wd, qa2, qb2);
    prologue_kv(xb + 2 * v * DD, kvbase + v * 24, s_wd, h2);

    __syncthreads();   // all K/V visible

    // ---- pair u ----
    {
        u64 o2[DD];
        attend(u, qa2, qb2, kvbase, o2);
        epilogue_pair(o2, xb + 2 * u * DD, ob + 2 * u * DD, s_wd);
    }

    // ---- pair v = 63-u ----
    make_q(h2, s_wd, qa2, qb2);
    {
        u64 o2[DD];
        attend(v, qa2, qb2, kvbase, o2);
        epilogue_pair(o2, xb + 2 * v * DD, ob + 2 * v * DD, s_wd);
    }
}

extern "C" void kernel_launch(void* const* d_in, const int* in_sizes, int n_in,
                              void* d_out, int out_size) {
    const float* x     = (const float*)d_in[0];
    const float* ln1_w = (const float*)d_in[1];
    const float* ln1_b = (const float*)d_in[2];
    const float* wqkv  = (const float*)d_in[3];
    const float* bqkv  = (const float*)d_in[4];
    const float* wo    = (const float*)d_in[5];
    const float* bo    = (const float*)d_in[6];
    const float* ln2_w = (const float*)d_in[7];
    const float* ln2_b = (const float*)d_in[8];
    const float* w1    = (const float*)d_in[9];
    const float* b1    = (const float*)d_in[10];
    const float* w2    = (const float*)d_in[11];
    const float* b2    = (const float*)d_in[12];
    float* out = (float*)d_out;

    const int B = in_sizes[0] / (SEQ * DD);   // 8192
    block_ffn_kernel<<<B / 4, 128>>>(x, ln1_w, ln1_b, wqkv, bqkv, wo, bo,
                                     ln2_w, ln2_b, w1, b1, w2, b2, out);
}